// round 2
// baseline (speedup 1.0000x reference)
#include <cuda_runtime.h>

#define HH 4096
#define WW 4096
#define BW 128          // columns per block
#define TPB 384         // BW * 3 channels, one thread per (col, chan)
#define CH 256          // rows per block chunk
#define WARM 44         // IIR warm-up rows (decay^44 ~ 2.7e-10)
#define RAD 4           // blur radius actually applied (tail <= 1.2e-8)
#define NT (2*RAD+1)
#define RING 9          // vertical blur ring
#define DRING 5         // d / soft ring (lag RAD)
#define STAGE_W (BW + 2*RAD)
#define STAGE_N (STAGE_W*3)

__global__ __launch_bounds__(TPB, 4)
void chem_kernel(const float* __restrict__ D, const float* __restrict__ Cm,
                 float* __restrict__ out)
{
    const int tid = threadIdx.x;
    const int c   = tid % 3;
    const int w0  = blockIdx.x * BW;
    const int h0  = blockIdx.y * CH;

    __shared__ float sh_stage[STAGE_N];
    __shared__ float sh_hb[RING][TPB];
    __shared__ float sh_d[DRING][TPB];
    __shared__ float sh_soft[DRING][TPB];
    __shared__ float sh_inh[TPB];

    // Gaussian weights: sigma=0.5, normalized over the full 25-tap window
    // (matches the reference), truncated to radius 4 for application.
    float kx[NT];
    {
        float z = 1.f;
        #pragma unroll
        for (int k = 1; k <= 12; ++k) z += 2.f * expf(-2.f * (float)(k*k));
        const float iz = 1.f / z;
        #pragma unroll
        for (int k = 0; k < NT; ++k) {
            int a = k - RAD; if (a < 0) a = -a;
            kx[k] = expf(-2.f * (float)(a*a)) * iz;
        }
    }

    const float DECAY = 0.60653065971263342f;   // exp(-0.5)
    const float OMD   = 1.f - DECAY;
    const float INV3  = 1.f / 3.000001f;        // 1/(d_max - d_min + 1e-6)

    // coupling column for this thread's output channel: out_j += C[i][j]*inh_i
    const float cc0 = __ldg(Cm + 0*3 + c);
    const float cc1 = __ldg(Cm + 1*3 + c);
    const float cc2 = __ldg(Cm + 2*3 + c);

    // prefetch lane mapping: element tid -> (col = tid/3, chan = tid%3)
    const int  colA = w0 - RAD + tid / 3;
    const bool okA  = (colA >= 0) && (colA < WW);
    const bool doB  = tid < (STAGE_N - TPB);     // 12 tail elements
    const int  colB = colA + BW;
    const bool okB  = doB && (colB >= 0) && (colB < WW);

    float s = 0.f;                  // IIR state (exact within chunk, warmed)
    int r = h0 - WARM;

    float pvA = 0.f, pvB = 0.f;
    if (r >= 0 && r < HH) {
        const float* rowp = D + (size_t)r * (WW*3);
        pvA = okA ? __ldg(rowp + colA*3 + c) : 0.f;
        pvB = okB ? __ldg(rowp + colB*3 + c) : 0.f;
    }

    int rm = ((r % RING)  + RING)  % RING;   // r mod 9
    int dm = ((r % DRING) + DRING) % DRING;  // r mod 5

    const int NITER = CH + WARM + RAD;
    for (int it = 0; it < NITER; ++it, ++r) {
        // commit prefetched row r into the stage
        sh_stage[tid] = pvA;
        if (doB) sh_stage[tid + TPB] = pvB;

        // prefetch row r+1 (LDG latency overlaps the barriers + compute below)
        float nA = 0.f, nB = 0.f;
        {
            const int rn = r + 1;
            if (rn >= 0 && rn < HH) {
                const float* rowp = D + (size_t)rn * (WW*3);
                nA = okA ? __ldg(rowp + colA*3 + c) : 0.f;
                nB = okB ? __ldg(rowp + colB*3 + c) : 0.f;
            }
        }
        __syncthreads();

        // horizontal blur + IIR update, push into rings
        float hb = 0.f;
        #pragma unroll
        for (int k = 0; k < NT; ++k) hb += kx[k] * sh_stage[tid + 3*k];
        const float dc = sh_stage[tid + 3*RAD];
        s = dc + DECAY * s;
        sh_hb[rm][tid]   = hb;
        sh_d[dm][tid]    = dc;
        sh_soft[dm][tid] = OMD * s;
        __syncthreads();

        const int  ro   = r - RAD;
        const bool emit = (ro >= h0) && (ro < h0 + CH);
        int dmo = dm + 1; if (dmo >= DRING) dmo = 0;   // ro mod 5
        if (emit) {
            float vb = 0.f;
            int b = rm + 1; if (b >= RING) b = 0;      // (ro-RAD) mod 9
            #pragma unroll
            for (int k = 0; k < NT; ++k) {
                vb += kx[k] * sh_hb[b][tid];
                ++b; if (b >= RING) b = 0;
            }
            const float dd = sh_d[dmo][tid];
            const float sf = sh_soft[dmo][tid];
            float m = dd * INV3;
            m = fminf(fmaxf(m, 0.f), 1.f);
            sh_inh[tid] = vb * m + sf * (1.f - m);
        }
        __syncthreads();

        if (emit) {
            const int wb = tid - c;
            const float i0 = sh_inh[wb + 0];
            const float i1 = sh_inh[wb + 1];
            const float i2 = sh_inh[wb + 2];
            const float dd = sh_d[dmo][tid];
            const float inh = cc0*i0 + cc1*i1 + cc2*i2;
            const float arg = (dd - inh) * INV3;
            float t;
            asm("tanh.approx.f32 %0, %1;" : "=f"(t) : "f"(arg));
            out[((size_t)ro * WW + w0) * 3 + tid] = 3.0f * t;
        }
        __syncthreads();

        pvA = nA; pvB = nB;
        ++rm; if (rm >= RING)  rm = 0;
        ++dm; if (dm >= DRING) dm = 0;
    }
}

extern "C" void kernel_launch(void* const* d_in, const int* in_sizes, int n_in,
                              void* d_out, int out_size)
{
    const float* D   = (const float*)d_in[0];   // (4096, 4096, 3) f32
    const float* Cm  = (const float*)d_in[1];   // (3, 3) f32
    float*       out = (float*)d_out;           // (4096, 4096, 3) f32
    dim3 grid(WW / BW, HH / CH);                // 32 x 16 = 512 blocks
    chem_kernel<<<grid, TPB>>>(D, Cm, out);
}